// round 1
// baseline (speedup 1.0000x reference)
#include <cuda_runtime.h>

#define Wn 262144
#define Ln 32
#define Nn (Ln * Wn)

// Scratch: per-node outputs (33.5 MB). Static device array per allocation rules.
__device__ float g_outs[Nn];

// Level 0: outs[i] = values[i] * w_term
__global__ void __launch_bounds__(256) level0_kernel(const float* __restrict__ values,
                                                     const float* __restrict__ w_term) {
    int i = (blockIdx.x * blockDim.x + threadIdx.x) * 4;
    float wt = __ldg(w_term);
    float4 v = *reinterpret_cast<const float4*>(values + i);
    float4 o;
    o.x = v.x * wt; o.y = v.y * wt; o.z = v.z * wt; o.w = v.w * wt;
    *reinterpret_cast<float4*>(g_outs + i) = o;
}

// Levels 1..31: gather 2 children, apply (+) or (-) linear map.
// Each thread handles 4 nodes: 2x int4 index loads, 1x int4 type load, float4 store.
__global__ void __launch_bounds__(256) level_kernel(
    const int4* __restrict__ idx4,    // level-local child_idx, [W,2] ints viewed as int4 (2 nodes each)
    const int4* __restrict__ typ4,    // level-local node_types, [W] ints viewed as int4 (4 nodes)
    const float2* __restrict__ wp,
    const float2* __restrict__ wm,
    int lvl_base)
{
    int t = blockIdx.x * blockDim.x + threadIdx.x;
    float2 P = __ldg(wp);
    float2 M = __ldg(wm);

    int4 a = __ldg(&idx4[2 * t]);       // nodes 4t, 4t+1
    int4 b = __ldg(&idx4[2 * t + 1]);   // nodes 4t+2, 4t+3
    int4 tt = __ldg(&typ4[t]);

    // 8 independent gathers (L2-resident)
    float x0a = __ldg(g_outs + a.x);
    float x0b = __ldg(g_outs + a.y);
    float x1a = __ldg(g_outs + a.z);
    float x1b = __ldg(g_outs + a.w);
    float x2a = __ldg(g_outs + b.x);
    float x2b = __ldg(g_outs + b.y);
    float x3a = __ldg(g_outs + b.z);
    float x3b = __ldg(g_outs + b.w);

    // Branch-free weight select per node
    float w00 = (tt.x == 1) ? P.x : M.x;
    float w01 = (tt.x == 1) ? P.y : M.y;
    float w10 = (tt.y == 1) ? P.x : M.x;
    float w11 = (tt.y == 1) ? P.y : M.y;
    float w20 = (tt.z == 1) ? P.x : M.x;
    float w21 = (tt.z == 1) ? P.y : M.y;
    float w30 = (tt.w == 1) ? P.x : M.x;
    float w31 = (tt.w == 1) ? P.y : M.y;

    float4 o;
    o.x = fmaf(w00, x0a, w01 * x0b);
    o.y = fmaf(w10, x1a, w11 * x1b);
    o.z = fmaf(w20, x2a, w21 * x2b);
    o.w = fmaf(w30, x3a, w31 * x3b);

    *reinterpret_cast<float4*>(g_outs + lvl_base + 4 * t) = o;
}

// Final affine on the last node.
__global__ void final_kernel(const float* __restrict__ w_final,
                             const float* __restrict__ b_final,
                             float* __restrict__ out) {
    out[0] = fmaf(g_outs[Nn - 1], w_final[0], b_final[0]);
}

extern "C" void kernel_launch(void* const* d_in, const int* in_sizes, int n_in,
                              void* d_out, int out_size) {
    const float* values     = (const float*)d_in[0];
    const int*   child_idx  = (const int*)d_in[1];   // [L-1, W, 2]
    const int*   node_types = (const int*)d_in[2];   // [L-1, W]
    const float* w_term     = (const float*)d_in[3];
    const float* w_plus     = (const float*)d_in[4];
    const float* w_minus    = (const float*)d_in[5];
    const float* w_final    = (const float*)d_in[6];
    const float* b_final    = (const float*)d_in[7];
    float* out = (float*)d_out;

    const int threads = 256;
    const int nodes_per_thread = 4;
    const int blocks = Wn / (threads * nodes_per_thread);  // 256

    level0_kernel<<<blocks, threads>>>(values, w_term);

    for (int l = 1; l < Ln; l++) {
        const int4* idx4 = (const int4*)(child_idx + (size_t)(l - 1) * Wn * 2);
        const int4* typ4 = (const int4*)(node_types + (size_t)(l - 1) * Wn);
        level_kernel<<<blocks, threads>>>(idx4, typ4,
                                          (const float2*)w_plus,
                                          (const float2*)w_minus,
                                          l * Wn);
    }

    final_kernel<<<1, 1>>>(w_final, b_final, out);
}